// round 1
// baseline (speedup 1.0000x reference)
#include <cuda_runtime.h>
#include <cstdint>
#include <cub/block/block_radix_sort.cuh>

// Problem constants
#define NT       4096                 // time samples per column (sort length)
#define NTRACES  512
#define CHANNELS 8
#define COLS     (NTRACES * CHANNELS) // 4096 columns
#define THREADS  512
#define IPT      8                    // items per thread (512*8 = 4096)
#define CH_PER_BLK 4                  // channels handled per block (float4 loads)
#define NBLOCKS  (NTRACES * (CHANNELS / CH_PER_BLK))  // 1024

using Sorter = cub::BlockRadixSort<float, THREADS, IPT>;

// Per-block partial sums (no device allocation allowed -> __device__ global)
__device__ float g_partials[NBLOCKS];

// Dynamic smem layout:
//   [0, 8*NT*4)                    : 8 column buffers (4 pred + 4 obs), 16KB each
//   [8*NT*4, +sizeof(TempStorage)) : cub radix sort temp storage (also reused
//                                    for the final block reduction scratch)
#define COLBUF_BYTES (8 * NT * 4)

__global__ __launch_bounds__(THREADS, 1)
void wass_sort_kernel(const float* __restrict__ pred, const float* __restrict__ obs)
{
    extern __shared__ unsigned char smem_raw[];
    float (*cols)[NT] = reinterpret_cast<float (*)[NT]>(smem_raw);
    typename Sorter::TempStorage* temp =
        reinterpret_cast<typename Sorter::TempStorage*>(smem_raw + COLBUF_BYTES);
    float* red = reinterpret_cast<float*>(smem_raw + COLBUF_BYTES); // overlaps temp (synced)

    const int tr = blockIdx.x >> 1;                // trace index
    const int c0 = (blockIdx.x & 1) * CH_PER_BLK;  // channel base (0 or 4)
    const int base = tr * CHANNELS + c0;           // column base within a time row

    // ---- Coalesced load: 4 adjacent channels per array via float4 ----
    for (int t = threadIdx.x; t < NT; t += THREADS) {
        const size_t off = (size_t)t * COLS + base;
        float4 p = *reinterpret_cast<const float4*>(pred + off);
        float4 o = *reinterpret_cast<const float4*>(obs  + off);
        cols[0][t] = p.x; cols[1][t] = p.y; cols[2][t] = p.z; cols[3][t] = p.w;
        cols[4][t] = o.x; cols[5][t] = o.y; cols[6][t] = o.z; cols[7][t] = o.w;
    }
    __syncthreads();

    float acc = 0.0f;
    const int tbase = threadIdx.x * IPT;

    #pragma unroll 1
    for (int c = 0; c < CH_PER_BLK; ++c) {
        float kp[IPT];
        #pragma unroll
        for (int i = 0; i < IPT; ++i) kp[i] = cols[c][tbase + i];

        Sorter(*temp).Sort(kp);         // sorted ascending, blocked arrangement
        __syncthreads();                // temp storage reuse barrier

        // write sorted pred back into its column buffer
        #pragma unroll
        for (int i = 0; i < IPT; ++i) cols[c][tbase + i] = kp[i];
        __syncthreads();

        float ko[IPT];
        #pragma unroll
        for (int i = 0; i < IPT; ++i) ko[i] = cols[CH_PER_BLK + c][tbase + i];

        Sorter(*temp).Sort(ko);
        __syncthreads();                // temp storage reuse barrier

        // |sorted_obs - sorted_pred| ; both in blocked arrangement
        #pragma unroll
        for (int i = 0; i < IPT; ++i) acc += fabsf(ko[i] - cols[c][tbase + i]);
    }

    // ---- Block reduction (deterministic) ----
    #pragma unroll
    for (int off = 16; off > 0; off >>= 1)
        acc += __shfl_xor_sync(0xFFFFFFFFu, acc, off);

    __syncthreads();   // done with temp storage before overlapping `red`
    const int wid  = threadIdx.x >> 5;
    const int lane = threadIdx.x & 31;
    if (lane == 0) red[wid] = acc;
    __syncthreads();

    if (wid == 0) {
        float v = (lane < THREADS / 32) ? red[lane] : 0.0f;
        #pragma unroll
        for (int off = 8; off > 0; off >>= 1)
            v += __shfl_xor_sync(0xFFFFFFFFu, v, off);
        if (lane == 0) g_partials[blockIdx.x] = v;
    }
}

// Final deterministic reduction of 1024 partials -> scalar mean
__global__ void wass_finalize_kernel(float* __restrict__ out)
{
    __shared__ double s[256];
    double acc = 0.0;
    for (int i = threadIdx.x; i < NBLOCKS; i += 256)
        acc += (double)g_partials[i];
    s[threadIdx.x] = acc;
    __syncthreads();
    for (int off = 128; off > 0; off >>= 1) {
        if (threadIdx.x < off) s[threadIdx.x] += s[threadIdx.x + off];
        __syncthreads();
    }
    if (threadIdx.x == 0)
        out[0] = (float)(s[0] / ((double)NT * (double)COLS));
}

extern "C" void kernel_launch(void* const* d_in, const int* in_sizes, int n_in,
                              void* d_out, int out_size)
{
    const float* pred = (const float*)d_in[0];
    const float* obs  = (const float*)d_in[1];
    float* out = (float*)d_out;

    const size_t smem_bytes = COLBUF_BYTES + sizeof(typename Sorter::TempStorage);
    cudaFuncSetAttribute(wass_sort_kernel,
                         cudaFuncAttributeMaxDynamicSharedMemorySize,
                         (int)smem_bytes);

    wass_sort_kernel<<<NBLOCKS, THREADS, smem_bytes>>>(pred, obs);
    wass_finalize_kernel<<<1, 256>>>(out);
}

// round 2
// speedup vs baseline: 1.3429x; 1.3429x over previous
#include <cuda_runtime.h>
#include <cstdint>
#include <cub/block/block_radix_sort.cuh>

// Problem constants
#define NT       4096                 // time samples per column (sort length)
#define NTRACES  512
#define CHANNELS 8
#define COLS     (NTRACES * CHANNELS) // 4096 columns
#define THREADS  512
#define IPT      8                    // items per thread (512*8 = 4096)
#define CH_PER_BLK 2                  // channels per block (float2 loads, 2 blocks/SM)
#define NBLOCKS  (NTRACES * (CHANNELS / CH_PER_BLK))  // 2048

// Sort only bits [8,32): low 8 mantissa bits left unsorted. Elements tied in
// the top 24 bits differ by < 2^-15 relative; induced error in the final mean
// is ~1e-4 relative, far under the 1e-3 gate, and fully deterministic.
#define BEGIN_BIT 8

using Sorter = cub::BlockRadixSort<float, THREADS, IPT>;

// No device allocation allowed -> __device__ globals for cross-block state.
__device__ float        g_partials[NBLOCKS];
__device__ unsigned int g_done = 0;

// Dynamic smem layout:
//   [0, 4*NT*4)  : 4 column buffers (2 pred + 2 obs), 16KB each = 64KB
//   [64KB, +T)   : cub radix sort temp storage
#define COLBUF_BYTES (2 * CH_PER_BLK * NT * 4)

__global__ __launch_bounds__(THREADS, 2)
void wass_fused_kernel(const float* __restrict__ pred,
                       const float* __restrict__ obs,
                       float* __restrict__ out)
{
    extern __shared__ unsigned char smem_raw[];
    float (*cols)[NT] = reinterpret_cast<float (*)[NT]>(smem_raw);
    typename Sorter::TempStorage* temp =
        reinterpret_cast<typename Sorter::TempStorage*>(smem_raw + COLBUF_BYTES);

    __shared__ float  sred[THREADS / 32];
    __shared__ double dred[THREADS / 32];
    __shared__ bool   s_last;

    const int tr   = blockIdx.x >> 2;               // trace index
    const int c0   = (blockIdx.x & 3) * CH_PER_BLK; // channel pair base
    const int base = tr * CHANNELS + c0;

    // ---- Coalesced-ish load: 2 adjacent channels via float2 (L2 dedups sectors) ----
    for (int t = threadIdx.x; t < NT; t += THREADS) {
        const size_t off = (size_t)t * COLS + base;
        float2 p = *reinterpret_cast<const float2*>(pred + off);
        float2 o = *reinterpret_cast<const float2*>(obs  + off);
        cols[0][t] = p.x; cols[1][t] = p.y;
        cols[2][t] = o.x; cols[3][t] = o.y;
    }
    __syncthreads();

    float acc = 0.0f;
    const int tbase = threadIdx.x * IPT;

    #pragma unroll 1
    for (int c = 0; c < CH_PER_BLK; ++c) {
        float kp[IPT];
        #pragma unroll
        for (int i = 0; i < IPT; ++i) kp[i] = cols[c][tbase + i];

        Sorter(*temp).Sort(kp, BEGIN_BIT, 32);
        __syncthreads();                 // temp reuse barrier

        #pragma unroll
        for (int i = 0; i < IPT; ++i) cols[c][tbase + i] = kp[i];
        __syncthreads();

        float ko[IPT];
        #pragma unroll
        for (int i = 0; i < IPT; ++i) ko[i] = cols[CH_PER_BLK + c][tbase + i];

        Sorter(*temp).Sort(ko, BEGIN_BIT, 32);
        __syncthreads();                 // temp reuse barrier

        #pragma unroll
        for (int i = 0; i < IPT; ++i) acc += fabsf(ko[i] - cols[c][tbase + i]);
    }

    // ---- Deterministic block reduction (float) ----
    #pragma unroll
    for (int off = 16; off > 0; off >>= 1)
        acc += __shfl_xor_sync(0xFFFFFFFFu, acc, off);

    const int wid  = threadIdx.x >> 5;
    const int lane = threadIdx.x & 31;
    if (lane == 0) sred[wid] = acc;
    __syncthreads();

    if (wid == 0) {
        float v = (lane < THREADS / 32) ? sred[lane] : 0.0f;
        #pragma unroll
        for (int off = 8; off > 0; off >>= 1)
            v += __shfl_xor_sync(0xFFFFFFFFu, v, off);
        if (lane == 0) g_partials[blockIdx.x] = v;
    }

    // ---- Last-block-done: fused final reduction (deterministic order) ----
    if (threadIdx.x == 0) {
        __threadfence();   // publish g_partials[blockIdx.x]
        unsigned int t = atomicAdd(&g_done, 1u);
        s_last = (t == NBLOCKS - 1);
    }
    __syncthreads();

    if (s_last) {
        __threadfence();   // acquire all partials
        double d = 0.0;
        for (int i = threadIdx.x; i < NBLOCKS; i += THREADS)
            d += (double)g_partials[i];
        // deterministic double reduction
        #pragma unroll
        for (int off = 16; off > 0; off >>= 1)
            d += __shfl_xor_sync(0xFFFFFFFFu, d, off);
        if (lane == 0) dred[wid] = d;
        __syncthreads();
        if (wid == 0) {
            double v = (lane < THREADS / 32) ? dred[lane] : 0.0;
            #pragma unroll
            for (int off = 8; off > 0; off >>= 1)
                v += __shfl_xor_sync(0xFFFFFFFFu, v, off);
            if (lane == 0) {
                out[0] = (float)(v / ((double)NT * (double)COLS));
                g_done = 0;   // reset for next graph replay
            }
        }
    }
}

extern "C" void kernel_launch(void* const* d_in, const int* in_sizes, int n_in,
                              void* d_out, int out_size)
{
    const float* pred = (const float*)d_in[0];
    const float* obs  = (const float*)d_in[1];
    float* out = (float*)d_out;

    const size_t smem_bytes = COLBUF_BYTES + sizeof(typename Sorter::TempStorage);
    cudaFuncSetAttribute(wass_fused_kernel,
                         cudaFuncAttributeMaxDynamicSharedMemorySize,
                         (int)smem_bytes);

    wass_fused_kernel<<<NBLOCKS, THREADS, smem_bytes>>>(pred, obs, out);
}

// round 3
// speedup vs baseline: 1.9360x; 1.4417x over previous
#include <cuda_runtime.h>
#include <cstdint>

#define NT       4096
#define NTRACES  512
#define CHANNELS 8
#define COLS     (NTRACES * CHANNELS)   // 4096
#define THREADS  512
#define IPT      8                      // 512*8 = 4096
#define NBINS    4096
#define CH_PER_BLK 2
#define NBLOCKS  (NTRACES * (CHANNELS / CH_PER_BLK))  // 2048

// Monotone linear bucket map over [-6, 6): exact sort regardless of clamping,
// because within-bucket cleanup sorts by true float value.
#define BIN_SCALE (4096.0f / 12.0f)

__device__ float        g_partials[NBLOCKS];
__device__ unsigned int g_done = 0;

// One exact counting sort: src (4096 floats, smem) -> dst (smem), using H (4096 u32).
// H is clobbered. All pointers are shared-memory. Block-wide collective.
__device__ __forceinline__ void counting_sort_4096(const float* __restrict__ src,
                                                   float* __restrict__ dst,
                                                   unsigned* __restrict__ H,
                                                   int tid)
{
    __shared__ unsigned wsum[THREADS / 32];

    // ---- zero histogram ----
    #pragma unroll
    for (int k = 0; k < NBINS / THREADS; ++k) H[tid + k * THREADS] = 0u;
    __syncthreads();

    // ---- histogram (smem atomics, spread addresses) ----
    #pragma unroll
    for (int k = 0; k < IPT; ++k) {
        float v = src[tid + k * THREADS];
        int b = __float2int_rd((v + 6.0f) * BIN_SCALE);
        b = min(max(b, 0), NBINS - 1);
        atomicAdd(&H[b], 1u);
    }
    __syncthreads();

    // ---- exclusive scan of H in place (8 consecutive bins per thread) ----
    unsigned loc[8];
    {
        uint4 h0 = reinterpret_cast<uint4*>(H)[tid * 2];
        uint4 h1 = reinterpret_cast<uint4*>(H)[tid * 2 + 1];
        loc[0] = h0.x; loc[1] = h0.y; loc[2] = h0.z; loc[3] = h0.w;
        loc[4] = h1.x; loc[5] = h1.y; loc[6] = h1.z; loc[7] = h1.w;
    }
    unsigned tsum = 0;
    #pragma unroll
    for (int k = 0; k < 8; ++k) { unsigned t = loc[k]; loc[k] = tsum; tsum += t; }

    const int lane = tid & 31, wid = tid >> 5;
    unsigned x = tsum;                      // inclusive warp scan of thread sums
    #pragma unroll
    for (int off = 1; off < 32; off <<= 1) {
        unsigned y = __shfl_up_sync(0xFFFFFFFFu, x, off);
        if (lane >= off) x += y;
    }
    if (lane == 31) wsum[wid] = x;
    __syncthreads();
    if (wid == 0) {
        unsigned w = (lane < THREADS / 32) ? wsum[lane] : 0u;
        #pragma unroll
        for (int off = 1; off < THREADS / 32; off <<= 1) {
            unsigned y = __shfl_up_sync(0xFFFFFFFFu, w, off);
            if (lane >= off) w += y;
        }
        if (lane < THREADS / 32) wsum[lane] = w;   // inclusive warp totals
    }
    __syncthreads();
    const unsigned base = (wid ? wsum[wid - 1] : 0u) + (x - tsum);
    #pragma unroll
    for (int k = 0; k < 8; ++k) loc[k] += base;
    {
        uint4 h0 = make_uint4(loc[0], loc[1], loc[2], loc[3]);
        uint4 h1 = make_uint4(loc[4], loc[5], loc[6], loc[7]);
        reinterpret_cast<uint4*>(H)[tid * 2]     = h0;
        reinterpret_cast<uint4*>(H)[tid * 2 + 1] = h1;
    }
    __syncthreads();

    // ---- scatter (H[b] becomes END offset of bucket b) ----
    #pragma unroll
    for (int k = 0; k < IPT; ++k) {
        float v = src[tid + k * THREADS];
        int b = __float2int_rd((v + 6.0f) * BIN_SCALE);
        b = min(max(b, 0), NBINS - 1);
        unsigned pos = atomicAdd(&H[b], 1u);
        dst[pos] = v;
    }
    __syncthreads();

    // ---- exact within-bucket cleanup (interleaved ownership for balance) ----
    for (int b = tid; b < NBINS; b += THREADS) {
        int hi = (int)H[b];
        int lo = b ? (int)H[b - 1] : 0;
        for (int i = lo + 1; i < hi; ++i) {
            float v = dst[i];
            int j = i - 1;
            while (j >= lo && dst[j] > v) { dst[j + 1] = dst[j]; --j; }
            dst[j + 1] = v;
        }
    }
    __syncthreads();
}

// Dynamic smem: W,X,Y,Z (inputs p0,p1,o0,o1), C (scratch dst), H -> 6 * 16KB = 96KB
__global__ __launch_bounds__(THREADS, 2)
void wass_count_kernel(const float* __restrict__ pred,
                       const float* __restrict__ obs,
                       float* __restrict__ out)
{
    extern __shared__ float smem[];
    float*    W = smem;               // pred ch0  -> later holds sorted obs ch0
    float*    X = smem + 4096;        // pred ch1  -> later holds sorted obs ch1
    float*    Y = smem + 8192;        // obs  ch0
    float*    Z = smem + 12288;       // obs  ch1
    float*    C = smem + 16384;       // sorted pred scratch
    unsigned* H = reinterpret_cast<unsigned*>(smem + 20480);

    __shared__ float  sred[THREADS / 32];
    __shared__ double dred[THREADS / 32];
    __shared__ bool   s_last;

    const int tid  = threadIdx.x;
    const int tr   = blockIdx.x >> 2;               // trace
    const int c0   = (blockIdx.x & 3) * CH_PER_BLK; // channel base (0,2,4,6)
    const int base = tr * CHANNELS + c0;

    // ---- load 2 adjacent channels per array via float2 (L2 dedups sectors) ----
    #pragma unroll
    for (int k = 0; k < IPT; ++k) {
        const int t = tid + k * THREADS;
        const size_t off = (size_t)t * COLS + base;
        float2 p = *reinterpret_cast<const float2*>(pred + off);
        float2 o = *reinterpret_cast<const float2*>(obs  + off);
        W[t] = p.x; X[t] = p.y; Y[t] = o.x; Z[t] = o.y;
    }
    __syncthreads();

    float acc = 0.0f;

    // channel 0: sort pred W -> C ; sort obs Y -> W ; diff
    counting_sort_4096(W, C, H, tid);
    counting_sort_4096(Y, W, H, tid);
    #pragma unroll
    for (int k = 0; k < IPT; ++k) {
        const int i = tid + k * THREADS;
        acc += fabsf(C[i] - W[i]);
    }
    __syncthreads();

    // channel 1: sort pred X -> C ; sort obs Z -> X ; diff
    counting_sort_4096(X, C, H, tid);
    counting_sort_4096(Z, X, H, tid);
    #pragma unroll
    for (int k = 0; k < IPT; ++k) {
        const int i = tid + k * THREADS;
        acc += fabsf(C[i] - X[i]);
    }

    // ---- deterministic block reduction ----
    #pragma unroll
    for (int off = 16; off > 0; off >>= 1)
        acc += __shfl_xor_sync(0xFFFFFFFFu, acc, off);

    const int wid  = tid >> 5;
    const int lane = tid & 31;
    if (lane == 0) sred[wid] = acc;
    __syncthreads();

    if (wid == 0) {
        float v = (lane < THREADS / 32) ? sred[lane] : 0.0f;
        #pragma unroll
        for (int off = 8; off > 0; off >>= 1)
            v += __shfl_xor_sync(0xFFFFFFFFu, v, off);
        if (lane == 0) g_partials[blockIdx.x] = v;
    }

    // ---- last-block-done fused finalize (deterministic) ----
    if (tid == 0) {
        __threadfence();
        unsigned int t = atomicAdd(&g_done, 1u);
        s_last = (t == NBLOCKS - 1);
    }
    __syncthreads();

    if (s_last) {
        __threadfence();
        double d = 0.0;
        for (int i = tid; i < NBLOCKS; i += THREADS)
            d += (double)g_partials[i];
        #pragma unroll
        for (int off = 16; off > 0; off >>= 1)
            d += __shfl_xor_sync(0xFFFFFFFFu, d, off);
        if (lane == 0) dred[wid] = d;
        __syncthreads();
        if (wid == 0) {
            double v = (lane < THREADS / 32) ? dred[lane] : 0.0;
            #pragma unroll
            for (int off = 8; off > 0; off >>= 1)
                v += __shfl_xor_sync(0xFFFFFFFFu, v, off);
            if (lane == 0) {
                out[0] = (float)(v / ((double)NT * (double)COLS));
                g_done = 0;   // reset for next graph replay
            }
        }
    }
}

extern "C" void kernel_launch(void* const* d_in, const int* in_sizes, int n_in,
                              void* d_out, int out_size)
{
    const float* pred = (const float*)d_in[0];
    const float* obs  = (const float*)d_in[1];
    float* out = (float*)d_out;

    const size_t smem_bytes = 6 * 4096 * sizeof(float);   // 96KB
    cudaFuncSetAttribute(wass_count_kernel,
                         cudaFuncAttributeMaxDynamicSharedMemorySize,
                         (int)smem_bytes);

    wass_count_kernel<<<NBLOCKS, THREADS, smem_bytes>>>(pred, obs, out);
}